// round 8
// baseline (speedup 1.0000x reference)
#include <cuda_runtime.h>
#include <cooperative_groups.h>
#include <cstdint>
#include <math.h>

namespace cg = cooperative_groups;

#define KNN 20
#define KLOC 8
#define MAXN 65536
#define FPS_CTAS 8
#define FPS_THREADS 256
#define FPS_TOTAL (FPS_CTAS * FPS_THREADS)
#define KNN_THREADS 128

typedef unsigned long long ull;

__device__ float4 g_pts[MAXN];
__device__ int    g_anchors[8192];
__device__ double g_acc;

__device__ __forceinline__ float dev_inf()  { return __int_as_float(0x7f800000); }
__device__ __forceinline__ float dev_ninf() { return __int_as_float(0xff800000); }
__device__ __forceinline__ ull pack_xy(float x, float y) {
    return ((ull)(unsigned)__float_as_int(y) << 32) | (unsigned)__float_as_int(x);
}

// ---------------------------------------------------------------------------
// Prep: AoS -> float4 SoA-of-structs, zero accumulator.
// ---------------------------------------------------------------------------
__global__ void prep_kernel(const float* __restrict__ pos, int N) {
    int i = blockIdx.x * blockDim.x + threadIdx.x;
    if (i == 0) g_acc = 0.0;
    int stride = gridDim.x * blockDim.x;
    for (int j = i; j < N; j += stride) {
        float4 p;
        p.x = pos[3 * j + 0];
        p.y = pos[3 * j + 1];
        p.z = pos[3 * j + 2];
        p.w = 0.f;
        g_pts[j] = p;
    }
}

// ---------------------------------------------------------------------------
// FPS: 8-CTA cluster, register-resident points + min-dist.
// ONE cluster.sync per iteration; candidate coords travel through DSMEM
// (double-buffered), so no global loads on the critical path.
// Distance chain bit-identical to reference-matching version:
// fp32, no FMA contraction, reduce order (dx2+dy2)+dz2. Tie-break min index
// via key = (d_bits<<32) | ~idx, u64 max.
// ---------------------------------------------------------------------------
template <int P>
__global__ void __cluster_dims__(FPS_CTAS, 1, 1) __launch_bounds__(FPS_THREADS, 1)
fps_kernel(int N, int n_anchors) {
    cg::cluster_group cluster = cg::this_cluster();
    const unsigned rank = cluster.block_rank();
    const int tid = threadIdx.x;
    const int g = (int)rank * FPS_THREADS + tid;

    float px[P], py[P], pz[P], md[P];
#pragma unroll
    for (int s = 0; s < P; s++) {
        int i = g + s * FPS_TOTAL;
        bool v = i < N;
        float4 p = v ? g_pts[i] : make_float4(0.f, 0.f, 0.f, 0.f);
        px[s] = p.x; py[s] = p.y; pz[s] = p.z;
        md[s] = v ? dev_inf() : dev_ninf();
    }

    __shared__ ull   wc_key[FPS_THREADS / 32];
    __shared__ ull   wc_xy[FPS_THREADS / 32];
    __shared__ float wc_z[FPS_THREADS / 32];
    __shared__ ull   cl_key[2][FPS_CTAS];
    __shared__ ull   cl_xy[2][FPS_CTAS];
    __shared__ float cl_z[2][FPS_CTAS];

    // first anchor = point 0
    float4 q0 = g_pts[0];
    float qx = q0.x, qy = q0.y, qz = q0.z;
    if (rank == 0 && tid == 0) g_anchors[0] = 0;

    for (int it = 1; it < n_anchors; ++it) {
        // ---- scan: update min-dist, track local argmax ----
        float bd = 0.0f;
        int bs = -1;
#pragma unroll
        for (int s = 0; s < P; s++) {
            float dx = __fsub_rn(px[s], qx);
            float dy = __fsub_rn(py[s], qy);
            float dz = __fsub_rn(pz[s], qz);
            float d  = __fadd_rn(__fadd_rn(__fmul_rn(dx, dx), __fmul_rn(dy, dy)),
                                 __fmul_rn(dz, dz));
            float m = fminf(md[s], d);
            md[s] = m;
            if (m > bd) { bd = m; bs = s; }   // ascending s => smallest idx on ties
        }
        unsigned bi = (bs >= 0) ? (unsigned)(g + bs * FPS_TOTAL) : 0x7fffffffu;
        ull key = ((ull)(unsigned)__float_as_int(bd) << 32) | (unsigned)(~bi);

        // ---- warp butterfly max (all lanes get warp max) ----
        ull wkey = key;
#pragma unroll
        for (int off = 16; off > 0; off >>= 1) {
            ull o = __shfl_xor_sync(0xffffffffu, wkey, off);
            if (o > wkey) wkey = o;
        }
        // unique winning lane recovers its best point's coords from registers
        if (key == wkey) {
            float bx = 0.f, by = 0.f, bz = 0.f;
#pragma unroll
            for (int s = 0; s < P; s++) {
                if (s == bs) { bx = px[s]; by = py[s]; bz = pz[s]; }
            }
            int w = tid >> 5;
            wc_key[w] = key;
            wc_xy[w]  = pack_xy(bx, by);
            wc_z[w]   = bz;
        }
        __syncthreads();

        const int buf = it & 1;
        if (tid < FPS_CTAS) {
            ull   k  = wc_key[tid];
            ull   xy = wc_xy[tid];
            float z  = wc_z[tid];
#pragma unroll
            for (int off = 4; off > 0; off >>= 1) {
                ull   ok  = __shfl_xor_sync(0x000000ffu, k, off);
                ull   oxy = __shfl_xor_sync(0x000000ffu, xy, off);
                float oz  = __shfl_xor_sync(0x000000ffu, z, off);
                if (ok > k) { k = ok; xy = oxy; z = oz; }
            }
            // every lane r ships this CTA's candidate to rank r
            *cluster.map_shared_rank(&cl_key[buf][rank], tid) = k;
            *cluster.map_shared_rank(&cl_xy[buf][rank], tid)  = xy;
            *cluster.map_shared_rank(&cl_z[buf][rank], tid)   = z;
        }
        cluster.sync();

        // ---- every thread picks the global winner locally ----
        ull wk = cl_key[buf][0];
        int wr = 0;
#pragma unroll
        for (int r = 1; r < FPS_CTAS; r++) {
            ull o = cl_key[buf][r];
            if (o > wk) { wk = o; wr = r; }
        }
        ull   xy = cl_xy[buf][wr];
        qx = __int_as_float((int)(unsigned)(xy & 0xffffffffull));
        qy = __int_as_float((int)(unsigned)(xy >> 32));
        qz = cl_z[buf][wr];

        if (rank == 0 && tid == 0) {
            g_anchors[it] = (int)(~(unsigned)(wk & 0xffffffffull));
        }
    }
}

// ---------------------------------------------------------------------------
// kNN: 2 anchors per block (point loads amortized), per-thread top-KLOC with
// cached float threshold on the hot path. Keys (d_bits<<32)|idx, d >= 0.
// Then 20 rounds of block-min selection + 3x3 PCA + loss term.
// ---------------------------------------------------------------------------
static __device__ const ull KEMPTY = 0x7f800000ffffffffull;  // d=+inf, idx=~0

__device__ __forceinline__ void knn_insert(ull (&ck)[KLOC], float& wf, int& wp,
                                           float d, int i) {
    ck[wp] = ((ull)(unsigned)__float_as_int(d) << 32) | (unsigned)i;
    ull w = 0; int q = 0;
#pragma unroll
    for (int k = 0; k < KLOC; k++) {
        if (ck[k] > w) { w = ck[k]; q = k; }
    }
    wf = __uint_as_float((unsigned)(w >> 32));
    wp = q;
}

__device__ __forceinline__ void select_and_pca(
    ull (&ck)[KLOC], int bcol, const float* __restrict__ vec_pred,
    ull* swk, ull* gwin_s, int* nn, float* sx, float* sy, float* sz)
{
    const int tid = threadIdx.x;
    for (int r = 0; r < KNN; r++) {
        ull lb = 0xffffffffffffffffull; int lp = -1;
#pragma unroll
        for (int k = 0; k < KLOC; k++) {
            if (ck[k] < lb) { lb = ck[k]; lp = k; }
        }
        ull rb = lb;
#pragma unroll
        for (int off = 16; off > 0; off >>= 1) {
            ull ob = __shfl_down_sync(0xffffffffu, rb, off);
            if (ob < rb) rb = ob;
        }
        if ((tid & 31) == 0) swk[tid >> 5] = rb;
        __syncthreads();
        if (tid == 0) {
            ull fb = swk[0];
#pragma unroll
            for (int w = 1; w < KNN_THREADS / 32; w++) {
                if (swk[w] < fb) fb = swk[w];
            }
            *gwin_s = fb;
            nn[r] = (int)(unsigned)(fb & 0xffffffffull);
        }
        __syncthreads();
        if (lp >= 0 && lb == *gwin_s) ck[lp] = 0xffffffffffffffffull;
    }
    __syncthreads();

    if (tid < KNN) {
        float4 p = g_pts[nn[tid]];
        sx[tid] = p.x; sy[tid] = p.y; sz[tid] = p.z;
    }
    __syncthreads();

    if (tid == 0) {
        double mx = 0, my = 0, mz = 0;
        for (int k = 0; k < KNN; k++) { mx += sx[k]; my += sy[k]; mz += sz[k]; }
        mx /= KNN; my /= KNN; mz /= KNN;
        double a00 = 0, a01 = 0, a02 = 0, a11 = 0, a12 = 0, a22 = 0;
        for (int k = 0; k < KNN; k++) {
            double cx = (double)sx[k] - mx;
            double cy = (double)sy[k] - my;
            double cz = (double)sz[k] - mz;
            a00 += cx * cx; a01 += cx * cy; a02 += cx * cz;
            a11 += cy * cy; a12 += cy * cz; a22 += cz * cz;
        }
        double vx = 1.0, vy = 0.0, vz = 0.0;
        double p1 = a01 * a01 + a02 * a02 + a12 * a12;
        if (p1 < 1e-300) {
            if (a00 >= a11 && a00 >= a22)      { vx = 1; vy = 0; vz = 0; }
            else if (a11 >= a22)               { vx = 0; vy = 1; vz = 0; }
            else                               { vx = 0; vy = 0; vz = 1; }
        } else {
            double q = (a00 + a11 + a22) / 3.0;
            double p2 = (a00 - q) * (a00 - q) + (a11 - q) * (a11 - q) +
                        (a22 - q) * (a22 - q) + 2.0 * p1;
            double p = sqrt(p2 / 6.0);
            double b00 = (a00 - q) / p, b11 = (a11 - q) / p, b22 = (a22 - q) / p;
            double b01 = a01 / p, b02 = a02 / p, b12 = a12 / p;
            double detB = b00 * (b11 * b22 - b12 * b12)
                        - b01 * (b01 * b22 - b12 * b02)
                        + b02 * (b01 * b12 - b11 * b02);
            double rr = fmin(1.0, fmax(-1.0, detB * 0.5));
            double phi = acos(rr) / 3.0;
            double lam = q + 2.0 * p * cos(phi);
            double m00 = a00 - lam, m11 = a11 - lam, m22 = a22 - lam;
            double c1x = a01 * a12 - a02 * m11;
            double c1y = a02 * a01 - m00 * a12;
            double c1z = m00 * m11 - a01 * a01;
            double c2x = a01 * m22 - a02 * a12;
            double c2y = a02 * a02 - m00 * m22;
            double c2z = m00 * a12 - a01 * a02;
            double c3x = m11 * m22 - a12 * a12;
            double c3y = a12 * a02 - a01 * m22;
            double c3z = a01 * a12 - m11 * a02;
            double n1 = c1x * c1x + c1y * c1y + c1z * c1z;
            double n2 = c2x * c2x + c2y * c2y + c2z * c2z;
            double n3 = c3x * c3x + c3y * c3y + c3z * c3z;
            double bx, by, bz, bn;
            if (n1 >= n2 && n1 >= n3)      { bx = c1x; by = c1y; bz = c1z; bn = n1; }
            else if (n2 >= n3)             { bx = c2x; by = c2y; bz = c2z; bn = n2; }
            else                           { bx = c3x; by = c3y; bz = c3z; bn = n3; }
            if (bn > 1e-300) {
                double inv = rsqrt(bn);
                vx = bx * inv; vy = by * inv; vz = bz * inv;
            }
        }
        double pax = (double)vec_pred[3 * bcol + 0];
        double pay = (double)vec_pred[3 * bcol + 1];
        double paz = (double)vec_pred[3 * bcol + 2];
        double na = fmax(sqrt(pax * pax + pay * pay + paz * paz), 1e-8);
        double nb = fmax(sqrt(vx * vx + vy * vy + vz * vz), 1e-8);
        double c = fabs(pax * vx + pay * vy + paz * vz) / (na * nb);
        atomicAdd(&g_acc, log(c + 1e-6));
    }
    __syncthreads();
}

__global__ void __launch_bounds__(KNN_THREADS)
knn_kernel(const float* __restrict__ vec_pred, int N, int n_anchors) {
    const int pb = blockIdx.x;
    const int tid = threadIdx.x;
    const int a0 = 2 * pb;
    const int a1 = 2 * pb + 1;
    const bool has1 = a1 < n_anchors;

    const int ai0 = g_anchors[a0];
    const int ai1 = has1 ? g_anchors[a1] : ai0;
    const float4 A0 = g_pts[ai0];
    const float4 A1 = g_pts[ai1];

    ull ck0[KLOC], ck1[KLOC];
#pragma unroll
    for (int k = 0; k < KLOC; k++) { ck0[k] = KEMPTY; ck1[k] = KEMPTY; }
    float wf0 = dev_inf();            int wp0 = 0;
    float wf1 = has1 ? dev_inf() : -1.0f;  int wp1 = 0;

#pragma unroll 2
    for (int i = tid; i < N; i += KNN_THREADS) {
        float4 p = __ldg(&g_pts[i]);
        float dx0 = p.x - A0.x, dy0 = p.y - A0.y, dz0 = p.z - A0.z;
        float d0 = fmaf(dx0, dx0, fmaf(dy0, dy0, dz0 * dz0));
        if (d0 < wf0) knn_insert(ck0, wf0, wp0, d0, i);
        float dx1 = p.x - A1.x, dy1 = p.y - A1.y, dz1 = p.z - A1.z;
        float d1 = fmaf(dx1, dx1, fmaf(dy1, dy1, dz1 * dz1));
        if (d1 < wf1) knn_insert(ck1, wf1, wp1, d1, i);
    }

    __shared__ ull swk[KNN_THREADS / 32];
    __shared__ ull gwin;
    __shared__ int nn[KNN];
    __shared__ float sx[KNN], sy[KNN], sz[KNN];

    select_and_pca(ck0, a0, vec_pred, swk, &gwin, nn, sx, sy, sz);
    if (has1) select_and_pca(ck1, a1, vec_pred, swk, &gwin, nn, sx, sy, sz);
}

__global__ void finalize_kernel(float* out, int n_anchors) {
    out[0] = (float)(-g_acc / (double)n_anchors);
}

// ---------------------------------------------------------------------------
extern "C" void kernel_launch(void* const* d_in, const int* in_sizes, int n_in,
                              void* d_out, int out_size) {
    const float* vec_pred = (const float*)d_in[0];
    const float* pos      = (const float*)d_in[1];
    int N = in_sizes[1] / 3;
    int n_anchors = (N + 9) / 10;  // ceil(0.1 * N)

    prep_kernel<<<64, 256>>>(pos, N);

    int P = (N + FPS_TOTAL - 1) / FPS_TOTAL;
    if (P <= 20) {
        fps_kernel<20><<<FPS_CTAS, FPS_THREADS>>>(N, n_anchors);
    } else {
        fps_kernel<32><<<FPS_CTAS, FPS_THREADS>>>(N, n_anchors);
    }

    int knn_blocks = (n_anchors + 1) / 2;
    knn_kernel<<<knn_blocks, KNN_THREADS>>>(vec_pred, N, n_anchors);
    finalize_kernel<<<1, 1>>>((float*)d_out, n_anchors);
}